// round 1
// baseline (speedup 1.0000x reference)
#include <cuda_runtime.h>
#include <cuda_bf16.h>

// Correlation: out[n,q,y,x] = (1/C) * sum_c d1[n,c,y,x] * d2pad[n,c,y+dy,x+dx]
// q = (dy+4)*9 + (dx+4), dy,dx in [-4,4]; d2 zero-padded outside [0,H)x[0,W).
// Shapes: N=8, C=256, H=96, W=160. Out: (8, 81, 96, 160) fp32.

#define CC   256
#define HH   96
#define WW   160
#define NN   8

constexpr int TQX  = 8;    // float4 groups per tile in x  -> 32 pixels
constexpr int TTY  = 16;   // y rows per tile
constexpr int KC   = 8;    // channel chunk in smem
constexpr int S1S  = 36;   // padded row stride (floats) for s1 (32 used)
constexpr int S2S  = 44;   // padded row stride (floats) for s2 (40 used)
constexpr int S2R  = 18;   // d2 rows needed: 16 + 2 (dy group span of 3)

__global__ __launch_bounds__(128, 2)
void corr_kernel(const float* __restrict__ d1,
                 const float* __restrict__ d2,
                 float* __restrict__ out)
{
    // blockIdx.x = g3 + 3*tile_x   (tile_x in [0,5), g3 = dy group in [0,3))
    // blockIdx.y = tile_y + 6*n    (tile_y in [0,6), n in [0,8))
    const int g3  = blockIdx.x % 3;
    const int tlx = blockIdx.x / 3;
    const int ty0 = (blockIdx.y % 6) * TTY;
    const int n   = blockIdx.y / 6;
    const int x0  = tlx * (TQX * 4);

    const int t   = threadIdx.x;   // 128 threads
    const int g   = t % TQX;       // x-group (4 pixels)
    const int tyl = t / TQX;       // 0..15

    __shared__ float s1[KC][TTY][S1S];
    __shared__ float s2[KC][S2R][S2S];

    float acc[3][9][4];
#pragma unroll
    for (int j = 0; j < 3; j++)
#pragma unroll
        for (int dxi = 0; dxi < 9; dxi++)
#pragma unroll
            for (int p = 0; p < 4; p++) acc[j][dxi][p] = 0.f;

    const int dy_base = 3 * g3 - 4;       // first dy of this group
    const int yb      = ty0 + dy_base;    // first global d2 row in smem
    const float* d1n = d1 + (size_t)n * CC * HH * WW;
    const float* d2n = d2 + (size_t)n * CC * HH * WW;

    for (int c0 = 0; c0 < CC; c0 += KC) {
        // ---- load d1 tile: KC x TTY x 32 floats (all in-bounds) ----
#pragma unroll
        for (int i = 0; i < (KC * TTY * TQX) / 128; i++) {
            int idx = t + i * 128;
            int xg  = idx % TQX;
            int yy  = (idx / TQX) % TTY;
            int cc  = idx / (TQX * TTY);
            float4 v = *reinterpret_cast<const float4*>(
                d1n + ((size_t)(c0 + cc) * HH + (ty0 + yy)) * WW + x0 + xg * 4);
            *reinterpret_cast<float4*>(&s1[cc][yy][xg * 4]) = v;
        }
        // ---- load d2 tile: KC x 18 rows x 40 floats, zero-padded ----
        for (int i = t; i < KC * S2R * 10; i += 128) {
            int xg = i % 10;
            int rr = (i / 10) % S2R;
            int cc = i / (10 * S2R);
            int gy = yb + rr;
            int gx = x0 - 4 + xg * 4;
            float4 v = make_float4(0.f, 0.f, 0.f, 0.f);
            if (gy >= 0 && gy < HH) {
                const float* rowp = d2n + ((size_t)(c0 + cc) * HH + gy) * WW;
                if (gx >= 0 && gx + 3 < WW) {
                    v = *reinterpret_cast<const float4*>(rowp + gx);
                } else {
                    float tv[4];
#pragma unroll
                    for (int e = 0; e < 4; e++) {
                        int xx = gx + e;
                        tv[e] = (xx >= 0 && xx < WW) ? rowp[xx] : 0.f;
                    }
                    v = make_float4(tv[0], tv[1], tv[2], tv[3]);
                }
            }
            *reinterpret_cast<float4*>(&s2[cc][rr][xg * 4]) = v;
        }
        __syncthreads();

        // ---- accumulate ----
        for (int c = 0; c < KC; c++) {
            const float4 a = *reinterpret_cast<const float4*>(&s1[c][tyl][g * 4]);
#pragma unroll
            for (int j = 0; j < 3; j++) {
                float b[12];
#pragma unroll
                for (int k = 0; k < 3; k++) {
                    float4 w = *reinterpret_cast<const float4*>(&s2[c][tyl + j][g * 4 + k * 4]);
                    b[k * 4 + 0] = w.x; b[k * 4 + 1] = w.y;
                    b[k * 4 + 2] = w.z; b[k * 4 + 3] = w.w;
                }
#pragma unroll
                for (int dxi = 0; dxi < 9; dxi++) {
                    acc[j][dxi][0] = fmaf(a.x, b[dxi + 0], acc[j][dxi][0]);
                    acc[j][dxi][1] = fmaf(a.y, b[dxi + 1], acc[j][dxi][1]);
                    acc[j][dxi][2] = fmaf(a.z, b[dxi + 2], acc[j][dxi][2]);
                    acc[j][dxi][3] = fmaf(a.w, b[dxi + 3], acc[j][dxi][3]);
                }
            }
        }
        __syncthreads();
    }

    // ---- epilogue: scale + store ----
    const float inv = 1.0f / (float)CC;
    const int y  = ty0 + tyl;
    const int xo = x0 + g * 4;
#pragma unroll
    for (int j = 0; j < 3; j++) {
        int dy = dy_base + j;
#pragma unroll
        for (int dxi = 0; dxi < 9; dxi++) {
            int q = (dy + 4) * 9 + dxi;
            float4 v = make_float4(acc[j][dxi][0] * inv, acc[j][dxi][1] * inv,
                                   acc[j][dxi][2] * inv, acc[j][dxi][3] * inv);
            *reinterpret_cast<float4*>(
                out + (((size_t)n * 81 + q) * HH + y) * WW + xo) = v;
        }
    }
}

extern "C" void kernel_launch(void* const* d_in, const int* in_sizes, int n_in,
                              void* d_out, int out_size)
{
    const float* data1 = (const float*)d_in[0];
    const float* data2 = (const float*)d_in[1];
    float* out = (float*)d_out;

    dim3 grid(3 * (WW / (TQX * 4)), (HH / TTY) * NN, 1);  // (15, 48)
    dim3 block(128, 1, 1);
    corr_kernel<<<grid, block>>>(data1, data2, out);
}

// round 2
// speedup vs baseline: 2.0070x; 2.0070x over previous
#include <cuda_runtime.h>
#include <cuda_bf16.h>

// Correlation: out[n,q,y,x] = (1/C) * sum_c d1[n,c,y,x] * d2pad[n,c,y+dy,x+dx]
// q = (dy+4)*9 + (dx+4), dy,dx in [-4,4]; d2 zero-padded outside [0,H)x[0,W).
// Shapes: N=8, C=256, H=96, W=160. Out: (8, 81, 96, 160) fp32.
//
// R2 design: 384-thread blocks = 3 dy-subsets x 128 threads. Each thread:
// 4 pixels x 9 dx x 1 dy = 36 accumulators (~70 regs). d1/d2 tiles shared
// in smem across the 3 dy subsets -> same global traffic as R1 but 3x the
// warps per SM to hide LDS latency.

#define CC   256
#define HH   96
#define WW   160
#define NN   8

constexpr int TQX  = 8;    // float4 groups per tile in x  -> 32 pixels
constexpr int TTY  = 16;   // y rows per tile
constexpr int KC   = 8;    // channel chunk in smem
constexpr int S1S  = 36;   // padded row stride (floats) for s1 (32 used)
constexpr int S2S  = 44;   // padded row stride (floats) for s2 (40 used)
constexpr int S2R  = 18;   // d2 rows needed: 16 + 2 (dy group span of 3)
constexpr int NT   = 384;  // threads per block

__global__ __launch_bounds__(NT, 2)
void corr_kernel(const float* __restrict__ d1,
                 const float* __restrict__ d2,
                 float* __restrict__ out)
{
    // blockIdx.x = g3 + 3*tile_x   (tile_x in [0,5), g3 = dy group in [0,3))
    // blockIdx.y = tile_y + 6*n    (tile_y in [0,6), n in [0,8))
    const int g3  = blockIdx.x % 3;
    const int tlx = blockIdx.x / 3;
    const int ty0 = (blockIdx.y % 6) * TTY;
    const int n   = blockIdx.y / 6;
    const int x0  = tlx * (TQX * 4);

    const int t    = threadIdx.x;      // 0..383
    const int tsub = t / 128;          // dy within group: 0..2
    const int tl   = t % 128;
    const int g    = tl % TQX;         // x-group (4 pixels)
    const int tyl  = tl / TQX;         // 0..15

    __shared__ float s1[KC][TTY][S1S];
    __shared__ float s2[KC][S2R][S2S];

    float acc[9][4];
#pragma unroll
    for (int dxi = 0; dxi < 9; dxi++)
#pragma unroll
        for (int p = 0; p < 4; p++) acc[dxi][p] = 0.f;

    const int dy_base = 3 * g3 - 4;       // first dy of this group
    const int yb      = ty0 + dy_base;    // first global d2 row in smem
    const float* d1n = d1 + (size_t)n * CC * HH * WW;
    const float* d2n = d2 + (size_t)n * CC * HH * WW;

    for (int c0 = 0; c0 < CC; c0 += KC) {
        // ---- load d1 tile: KC x TTY x 32 floats (all in-bounds) ----
        // 1024 float4 across 384 threads
        for (int i = t; i < KC * TTY * TQX; i += NT) {
            int xg  = i % TQX;
            int yy  = (i / TQX) % TTY;
            int cc  = i / (TQX * TTY);
            float4 v = *reinterpret_cast<const float4*>(
                d1n + ((size_t)(c0 + cc) * HH + (ty0 + yy)) * WW + x0 + xg * 4);
            *reinterpret_cast<float4*>(&s1[cc][yy][xg * 4]) = v;
        }
        // ---- load d2 tile: KC x 18 rows x 40 floats, zero-padded ----
        for (int i = t; i < KC * S2R * 10; i += NT) {
            int xg = i % 10;
            int rr = (i / 10) % S2R;
            int cc = i / (10 * S2R);
            int gy = yb + rr;
            int gx = x0 - 4 + xg * 4;
            float4 v = make_float4(0.f, 0.f, 0.f, 0.f);
            if (gy >= 0 && gy < HH) {
                const float* rowp = d2n + ((size_t)(c0 + cc) * HH + gy) * WW;
                if (gx >= 0 && gx + 3 < WW) {
                    v = *reinterpret_cast<const float4*>(rowp + gx);
                } else {
                    float tv[4];
#pragma unroll
                    for (int e = 0; e < 4; e++) {
                        int xx = gx + e;
                        tv[e] = (xx >= 0 && xx < WW) ? rowp[xx] : 0.f;
                    }
                    v = make_float4(tv[0], tv[1], tv[2], tv[3]);
                }
            }
            *reinterpret_cast<float4*>(&s2[cc][rr][xg * 4]) = v;
        }
        __syncthreads();

        // ---- accumulate: 1 dy per thread (tsub), 9 dx, 4 px ----
#pragma unroll
        for (int c = 0; c < KC; c++) {
            const float4 a = *reinterpret_cast<const float4*>(&s1[c][tyl][g * 4]);
            float b[12];
#pragma unroll
            for (int k = 0; k < 3; k++) {
                float4 w = *reinterpret_cast<const float4*>(
                    &s2[c][tyl + tsub][g * 4 + k * 4]);
                b[k * 4 + 0] = w.x; b[k * 4 + 1] = w.y;
                b[k * 4 + 2] = w.z; b[k * 4 + 3] = w.w;
            }
#pragma unroll
            for (int dxi = 0; dxi < 9; dxi++) {
                acc[dxi][0] = fmaf(a.x, b[dxi + 0], acc[dxi][0]);
                acc[dxi][1] = fmaf(a.y, b[dxi + 1], acc[dxi][1]);
                acc[dxi][2] = fmaf(a.z, b[dxi + 2], acc[dxi][2]);
                acc[dxi][3] = fmaf(a.w, b[dxi + 3], acc[dxi][3]);
            }
        }
        __syncthreads();
    }

    // ---- epilogue: scale + store ----
    const float inv = 1.0f / (float)CC;
    const int y  = ty0 + tyl;
    const int xo = x0 + g * 4;
    const int dy = dy_base + tsub;
#pragma unroll
    for (int dxi = 0; dxi < 9; dxi++) {
        int q = (dy + 4) * 9 + dxi;
        float4 v = make_float4(acc[dxi][0] * inv, acc[dxi][1] * inv,
                               acc[dxi][2] * inv, acc[dxi][3] * inv);
        *reinterpret_cast<float4*>(
            out + (((size_t)n * 81 + q) * HH + y) * WW + xo) = v;
    }
}

extern "C" void kernel_launch(void* const* d_in, const int* in_sizes, int n_in,
                              void* d_out, int out_size)
{
    const float* data1 = (const float*)d_in[0];
    const float* data2 = (const float*)d_in[1];
    float* out = (float*)d_out;

    dim3 grid(3 * (WW / (TQX * 4)), (HH / TTY) * NN, 1);  // (15, 48)
    dim3 block(NT, 1, 1);
    corr_kernel<<<grid, block>>>(data1, data2, out);
}

// round 3
// speedup vs baseline: 4.3169x; 2.1509x over previous
#include <cuda_runtime.h>
#include <cuda_bf16.h>
#include <cstdint>

// Correlation: out[n,q,y,x] = (1/C) * sum_c d1[n,c,y,x] * d2pad[n,c,y+dy,x+dx]
// q = (dy+4)*9 + (dx+4), dy,dx in [-4,4]; d2 zero-padded outside [0,H)x[0,W).
// Shapes: N=8, C=256, H=96, W=160. Out: (8, 81, 96, 160) fp32.
//
// R3: R2 tiling + 2-stage cp.async double buffer so global latency is hidden
// behind FFMA of the previous chunk.

#define CC   256
#define HH   96
#define WW   160
#define NN   8

constexpr int TQX  = 8;    // float4 groups per tile in x  -> 32 pixels
constexpr int TTY  = 16;   // y rows per tile
constexpr int KC   = 8;    // channel chunk in smem
constexpr int S1S  = 36;   // padded row stride (floats) for s1 (32 used)
constexpr int S2S  = 44;   // padded row stride (floats) for s2 (40 used)
constexpr int S2R  = 18;   // d2 rows needed: 16 + 2 (dy group span of 3)
constexpr int NT   = 384;  // threads per block
constexpr int NCH  = CC / KC;               // 32 chunks
constexpr int S1_F = KC * TTY * S1S;        // 4608 floats
constexpr int S2_F = KC * S2R * S2S;        // 6336 floats
constexpr int STAGE_F = S1_F + S2_F;        // 10944 floats
constexpr int SMEM_BYTES = 2 * STAGE_F * 4; // 87552 bytes

__device__ __forceinline__ void cp16(uint32_t dst, const void* src, bool p) {
    asm volatile("cp.async.cg.shared.global [%0], [%1], 16, %2;\n"
                 :: "r"(dst), "l"(src), "r"(p ? 16 : 0));
}
__device__ __forceinline__ void cp_commit() {
    asm volatile("cp.async.commit_group;\n" ::: "memory");
}
template <int N>
__device__ __forceinline__ void cp_wait() {
    asm volatile("cp.async.wait_group %0;\n" :: "n"(N) : "memory");
}

__global__ __launch_bounds__(NT, 2)
void corr_kernel(const float* __restrict__ d1,
                 const float* __restrict__ d2,
                 float* __restrict__ out)
{
    extern __shared__ float smem[];

    // blockIdx.x = g3 + 3*tile_x ; blockIdx.y = tile_y + 6*n
    const int g3  = blockIdx.x % 3;
    const int tlx = blockIdx.x / 3;
    const int ty0 = (blockIdx.y % 6) * TTY;
    const int n   = blockIdx.y / 6;
    const int x0  = tlx * (TQX * 4);

    const int t    = threadIdx.x;      // 0..383
    const int tsub = t / 128;          // dy within group: 0..2
    const int tl   = t % 128;
    const int g    = tl % TQX;         // x-group (4 pixels)
    const int tyl  = tl / TQX;         // 0..15

    float acc[9][4];
#pragma unroll
    for (int dxi = 0; dxi < 9; dxi++)
#pragma unroll
        for (int p = 0; p < 4; p++) acc[dxi][p] = 0.f;

    const int dy_base = 3 * g3 - 4;
    const int yb      = ty0 + dy_base;
    const float* d1n = d1 + (size_t)n * CC * HH * WW;
    const float* d2n = d2 + (size_t)n * CC * HH * WW;

    const uint32_t smem_u32 = (uint32_t)__cvta_generic_to_shared(smem);

    // ---- async load of one chunk into a given stage ----
    auto load_stage = [&](int stage, int c0) {
        const uint32_t s1b = smem_u32 + (uint32_t)(stage * STAGE_F) * 4u;
        const uint32_t s2b = s1b + (uint32_t)S1_F * 4u;
        // d1 tile: KC x TTY x 32 floats, all in-bounds
        for (int i = t; i < KC * TTY * TQX; i += NT) {
            int xg = i % TQX;
            int yy = (i / TQX) % TTY;
            int cc = i / (TQX * TTY);
            const float* src =
                d1n + ((size_t)(c0 + cc) * HH + (ty0 + yy)) * WW + x0 + xg * 4;
            uint32_t dst = s1b + (uint32_t)(((cc * TTY + yy) * S1S + xg * 4) * 4);
            cp16(dst, src, true);
        }
        // d2 tile: KC x 18 x 40 floats; every 16B vector fully in or out.
        for (int i = t; i < KC * S2R * 10; i += NT) {
            int xg = i % 10;
            int rr = (i / 10) % S2R;
            int cc = i / (10 * S2R);
            int gy = yb + rr;
            int gx = x0 - 4 + xg * 4;
            bool ok = (gy >= 0) && (gy < HH) && (gx >= 0) && (gx + 3 < WW);
            const float* src = ok
                ? d2n + ((size_t)(c0 + cc) * HH + gy) * WW + gx
                : d2n;  // valid dummy address; 0 bytes read when !ok
            uint32_t dst = s2b + (uint32_t)(((cc * S2R + rr) * S2S + xg * 4) * 4);
            cp16(dst, src, ok);
        }
        cp_commit();
    };

    // ---- prologue ----
    load_stage(0, 0);

    int stage = 0;
    for (int it = 0; it < NCH; it++) {
        if (it + 1 < NCH) {
            load_stage(stage ^ 1, (it + 1) * KC);
            cp_wait<1>();   // current stage's group complete
        } else {
            cp_wait<0>();
        }
        __syncthreads();

        const float* s1c = smem + stage * STAGE_F;
        const float* s2c = s1c + S1_F;

#pragma unroll
        for (int c = 0; c < KC; c++) {
            const float4 a = *reinterpret_cast<const float4*>(
                &s1c[(c * TTY + tyl) * S1S + g * 4]);
            float b[12];
#pragma unroll
            for (int k = 0; k < 3; k++) {
                float4 w = *reinterpret_cast<const float4*>(
                    &s2c[(c * S2R + tyl + tsub) * S2S + g * 4 + k * 4]);
                b[k * 4 + 0] = w.x; b[k * 4 + 1] = w.y;
                b[k * 4 + 2] = w.z; b[k * 4 + 3] = w.w;
            }
#pragma unroll
            for (int dxi = 0; dxi < 9; dxi++) {
                acc[dxi][0] = fmaf(a.x, b[dxi + 0], acc[dxi][0]);
                acc[dxi][1] = fmaf(a.y, b[dxi + 1], acc[dxi][1]);
                acc[dxi][2] = fmaf(a.z, b[dxi + 2], acc[dxi][2]);
                acc[dxi][3] = fmaf(a.w, b[dxi + 3], acc[dxi][3]);
            }
        }
        __syncthreads();   // protect the buffer the next prefetch overwrites
        stage ^= 1;
    }

    // ---- epilogue: scale + store ----
    const float inv = 1.0f / (float)CC;
    const int y  = ty0 + tyl;
    const int xo = x0 + g * 4;
    const int dy = dy_base + tsub;
#pragma unroll
    for (int dxi = 0; dxi < 9; dxi++) {
        int q = (dy + 4) * 9 + dxi;
        float4 v = make_float4(acc[dxi][0] * inv, acc[dxi][1] * inv,
                               acc[dxi][2] * inv, acc[dxi][3] * inv);
        *reinterpret_cast<float4*>(
            out + (((size_t)n * 81 + q) * HH + y) * WW + xo) = v;
    }
}

extern "C" void kernel_launch(void* const* d_in, const int* in_sizes, int n_in,
                              void* d_out, int out_size)
{
    const float* data1 = (const float*)d_in[0];
    const float* data2 = (const float*)d_in[1];
    float* out = (float*)d_out;

    cudaFuncSetAttribute(corr_kernel,
                         cudaFuncAttributeMaxDynamicSharedMemorySize,
                         SMEM_BYTES);

    dim3 grid(3 * (WW / (TQX * 4)), (HH / TTY) * NN, 1);  // (15, 48)
    dim3 block(NT, 1, 1);
    corr_kernel<<<grid, block, SMEM_BYTES>>>(data1, data2, out);
}